// round 15
// baseline (speedup 1.0000x reference)
#include <cuda_runtime.h>
#include <cuda_bf16.h>
#include <math.h>
#include <stdint.h>

// ---------------- problem constants ----------------
#define OHW         254
#define STRIP_OROWS 16
#define STRIPS      16
#define ITERS       16          // 256 output pixels per iteration
#define NCHUNKS     36          // buildable 128-row input chunks per strip
#define RING_ROWS   1280        // 10-chunk ring
#define PITCH       48          // bytes per A/B row (32 data + 16 pad; conflict-free)
#define OFF_RED     0           // 2 x 512 floats (ping-pong)
#define OFF_B       4096        // 9 tiles x 64 rows x 48B = 27648
#define OFF_A       (4096 + 27648)                  // 31744
#define SMEM_BYTES  (OFF_A + RING_ROWS * PITCH)     // 93184 (x2 CTAs = 186368)

__device__ __forceinline__ uint32_t smem_u32(const void* p) {
    uint32_t a;
    asm("{ .reg .u64 t; cvta.to.shared.u64 t, %1; cvt.u32.u64 %0, t; }"
        : "=r"(a) : "l"(p));
    return a;
}
__device__ __forceinline__ void ldmatrix_x4(uint32_t& a0, uint32_t& a1,
                                            uint32_t& a2, uint32_t& a3,
                                            uint32_t addr) {
    asm volatile("ldmatrix.sync.aligned.m8n8.x4.shared.b16 {%0,%1,%2,%3}, [%4];"
                 : "=r"(a0), "=r"(a1), "=r"(a2), "=r"(a3) : "r"(addr));
}
__device__ __forceinline__ void mma_bf16(float* c, uint32_t a0, uint32_t a1,
                                         uint32_t a2, uint32_t a3,
                                         uint32_t b0, uint32_t b1) {
    asm volatile(
        "mma.sync.aligned.m16n8k16.row.col.f32.bf16.bf16.f32 "
        "{%0,%1,%2,%3}, {%4,%5,%6,%7}, {%8,%9}, {%0,%1,%2,%3};"
        : "+f"(c[0]), "+f"(c[1]), "+f"(c[2]), "+f"(c[3])
        : "r"(a0), "r"(a1), "r"(a2), "r"(a3), "r"(b0), "r"(b1));
}
__device__ __forceinline__ uint32_t pkbf(float lo, float hi) {
    __nv_bfloat162 t = __float22bfloat162_rn(make_float2(lo, hi));
    return *reinterpret_cast<uint32_t*>(&t);
}

extern __shared__ char smem[];

// A-fragment smem address for (kh, kw, mt), ring-wrapped.
__device__ __forceinline__ uint32_t a_addr(const int* rks, int kh, int kw, int mt,
                                           uint32_t a_base, uint32_t a_col_off) {
    int row = rks[kh] + kw + mt * 16;
    if (row >= RING_ROWS) row -= RING_ROWS;
    return a_base + (uint32_t)(row * PITCH) + a_col_off;
}

// Load 16 channel values for one pixel row, converting to 8 packed bf16x2.
__device__ __forceinline__ void load16_u(int c0, int oy0,
                                         const float* __restrict__ xb,
                                         int tid, uint32_t* u) {
    const int p  = c0 * 128 + tid;
    const int iy = oy0 + (p >> 8);
    const int ix = p & 255;
    if (iy < 256) {
        const float* xp = xb + iy * 256 + ix;
        #pragma unroll
        for (int j = 0; j < 8; j++) {
            const float a = __ldg(xp + ((2 * j) << 16));
            const float c = __ldg(xp + ((2 * j + 1) << 16));
            u[j] = pkbf(a, c);
        }
    } else {
        #pragma unroll
        for (int j = 0; j < 8; j++) u[j] = 0u;
    }
}
// Store one staged pixel row at a pre-wrapped ring row.
__device__ __forceinline__ void store16_at(int ring_row, const uint32_t* u) {
    char* base = smem + OFF_A + ring_row * PITCH;
    *reinterpret_cast<uint4*>(base)      = make_uint4(u[0], u[1], u[2], u[3]);
    *reinterpret_cast<uint4*>(base + 16) = make_uint4(u[4], u[5], u[6], u[7]);
}

__global__ __launch_bounds__(256, 2)
void conv_mma_kernel(const float* __restrict__ x, const float* __restrict__ w,
                     const float* __restrict__ bias, float* __restrict__ out)
{
    const int tid  = threadIdx.x;
    const int warp = tid >> 5;
    const int lane = tid & 31;
    const int g    = lane >> 2;       // fragment group (row / n index)
    const int q    = lane & 3;        // thread-in-group
    const int nh   = warp & 1;        // n-half: couts [nh*32, nh*32+32)
    const int mq   = warp >> 1;       // m-quarter: rows [mq*64, mq*64+64) of 256

    const int strip = blockIdx.x;
    const int b     = blockIdx.y;
    const int oy0   = strip * STRIP_OROWS;
    const uint32_t sbase = smem_u32(smem);
    float* red = (float*)(smem + OFF_RED);

    // ---- B: 9 tiles (kh*3+kw), rows = cout n, 16 ci bf16 per row ----
    for (int idx = tid; idx < 9 * 64 * 16; idx += 256) {
        const int t  = idx >> 10;
        const int rm = idx & 1023;
        const int n  = rm >> 4;
        const int ci = rm & 15;
        const float val = __ldg(w + n * 144 + ci * 9 + t);
        *reinterpret_cast<__nv_bfloat16*>(smem + OFF_B + t * (64 * PITCH)
                                          + n * PITCH + ci * 2) = __float2bfloat16(val);
    }

    // loop-invariant bias (8 regs)
    float blo[4], bhi[4];
    #pragma unroll
    for (int nt = 0; nt < 4; nt++) {
        blo[nt] = __ldg(bias + nh * 32 + nt * 8 + 2 * q);
        bhi[nt] = __ldg(bias + nh * 32 + nt * 8 + 2 * q + 1);
    }

    const float* xb = x + ((size_t)b << 20);

    // lane-constant pieces of ldmatrix addresses
    const uint32_t a_col_off  = (uint32_t)((lane >> 4) << 4);
    const uint32_t b_lane_off = (uint32_t)((((lane >> 3) >> 1) * 8 + (lane & 7)) * PITCH
                                           + (((lane >> 3) & 1) << 4));
    const uint32_t b_base = sbase + OFF_B + (uint32_t)(nh * 32 * PITCH) + b_lane_off;
    const uint32_t a_base = sbase + OFF_A;

    // ---- prologue: chunks 0..7 (rows 0..1023, no wrap) ----
    #pragma unroll 1
    for (int j = 0; j < 4; j++) {
        uint32_t u[8];
        load16_u(2 * j, oy0, xb, tid, u);
        store16_at(2 * j * 128 + tid, u);
    }
    __syncthreads();

    // incremental ring bases (both already in [0, RING_ROWS))
    int sts_row = 1024 + tid;                 // ring row of chunk-8 + tid
    int a_row0  = mq * 64 + (lane & 15);      // warp's M base for i=0

    // ---- main pipeline: ONE barrier per iteration ----
    #pragma unroll 1
    for (int i = 0; i < ITERS; i++) {
        // deferred epilogue part 2 of iteration i-1 (overlaps this MMA block)
        if (i > 0) {
            const float* redp = red + ((i - 1) & 1) * 512;
            float mm = fminf(redp[2 * tid], redp[2 * tid + 1]);
            float y  = tanhf(tanhf(mm));
            const int p  = (i - 1) * 256 + tid;
            const int oy = oy0 + (p >> 8);
            const int ox = p & 255;
            if (ox < OHW && oy < OHW)
                out[((size_t)b * OHW + oy) * OHW + ox] = y;
        }

        // stage next build's LDGs (chunks 2i+8, 2i+9), convert at load
        const int c0 = 2 * i + 8;
        uint32_t u[8];
        if (c0 < NCHUNKS) load16_u(c0, oy0, xb, tid, u);

        float acc[4][4][4];
        #pragma unroll
        for (int mt = 0; mt < 4; mt++)
            #pragma unroll
            for (int nt = 0; nt < 4; nt++) {
                acc[mt][nt][0] = blo[nt]; acc[mt][nt][1] = bhi[nt];
                acc[mt][nt][2] = blo[nt]; acc[mt][nt][3] = bhi[nt];
            }

        // wrapped kh row bases
        int rks[3];
        #pragma unroll
        for (int kh = 0; kh < 3; kh++) {
            int rk = a_row0 + kh * 256;
            if (rk >= RING_ROWS) rk -= RING_ROWS;
            rks[kh] = rk;
        }

        // 9 shift-steps, BOTH operand streams software-pipelined:
        //   bf[2][8]: B(step+1) loaded at top of step
        //   af[2][4]: A(step, mt+1) loaded before the MMAs of (step, mt)
        uint32_t af[2][4], bf[2][8];
        ldmatrix_x4(af[0][0], af[0][1], af[0][2], af[0][3],
                    a_addr(rks, 0, 0, 0, a_base, a_col_off));
        ldmatrix_x4(bf[0][0], bf[0][1], bf[0][2], bf[0][3], b_base);
        ldmatrix_x4(bf[0][4], bf[0][5], bf[0][6], bf[0][7], b_base + 16 * PITCH);

        #pragma unroll
        for (int step = 0; step < 9; step++) {
            const int kh = step / 3;
            const int kw = step - kh * 3;
            const int bc = step & 1;
            if (step < 8) {   // prefetch next step's B fragments
                const uint32_t bt = b_base + (uint32_t)((step + 1) * 64 * PITCH);
                ldmatrix_x4(bf[bc ^ 1][0], bf[bc ^ 1][1], bf[bc ^ 1][2],
                            bf[bc ^ 1][3], bt);
                ldmatrix_x4(bf[bc ^ 1][4], bf[bc ^ 1][5], bf[bc ^ 1][6],
                            bf[bc ^ 1][7], bt + 16 * PITCH);
            }
            #pragma unroll
            for (int mt = 0; mt < 4; mt++) {
                const int ac = (step * 4 + mt) & 1;
                // prefetch the NEXT A fragment before using the current one
                if (mt < 3) {
                    ldmatrix_x4(af[ac ^ 1][0], af[ac ^ 1][1], af[ac ^ 1][2],
                                af[ac ^ 1][3],
                                a_addr(rks, kh, kw, mt + 1, a_base, a_col_off));
                } else if (step < 8) {
                    const int ns  = step + 1;
                    const int nkh = ns / 3;
                    const int nkw = ns - nkh * 3;
                    ldmatrix_x4(af[ac ^ 1][0], af[ac ^ 1][1], af[ac ^ 1][2],
                                af[ac ^ 1][3],
                                a_addr(rks, nkh, nkw, 0, a_base, a_col_off));
                }
                #pragma unroll
                for (int nt = 0; nt < 4; nt++)
                    mma_bf16(acc[mt][nt], af[ac][0], af[ac][1], af[ac][2],
                             af[ac][3], bf[bc][nt * 2], bf[bc][nt * 2 + 1]);
            }
        }

        // ---- epilogue part 1: min over this warp's 32 couts -> red[i&1] ----
        float m[8];
        #pragma unroll
        for (int mt = 0; mt < 4; mt++) {
            float lo = fminf(acc[mt][0][0], acc[mt][0][1]);
            float hi = fminf(acc[mt][0][2], acc[mt][0][3]);
            #pragma unroll
            for (int nt = 1; nt < 4; nt++) {
                lo = fminf(lo, fminf(acc[mt][nt][0], acc[mt][nt][1]));
                hi = fminf(hi, fminf(acc[mt][nt][2], acc[mt][nt][3]));
            }
            m[2 * mt]     = lo;   // row mq*64 + mt*16 + g
            m[2 * mt + 1] = hi;   // row mq*64 + mt*16 + g + 8
        }
        #pragma unroll
        for (int j = 0; j < 8; j++) {
            m[j] = fminf(m[j], __shfl_xor_sync(0xFFFFFFFFu, m[j], 1));
            m[j] = fminf(m[j], __shfl_xor_sync(0xFFFFFFFFu, m[j], 2));
        }
        float* redp = red + (i & 1) * 512;
        if (q == 0) {
            const int rb = mq * 64 + g;
            #pragma unroll
            for (int j = 0; j < 8; j++)
                redp[(rb + j * 8) * 2 + nh] = m[j];
        }

        // commit staged build — chunks 2i+8,2i+9 are disjoint from the read
        // window (2i..2i+6) in the 10-chunk ring: no extra barrier needed
        if (c0 < NCHUNKS) store16_at(sts_row, u);

        // single barrier: STS(i)->reads(i+1); red writes->part2; part2->rewrite
        __syncthreads();

        a_row0 += 256; if (a_row0 >= RING_ROWS) a_row0 -= RING_ROWS;
        sts_row += 256; if (sts_row >= RING_ROWS) sts_row -= RING_ROWS;
    }

    // final deferred epilogue (iteration ITERS-1)
    {
        const float* redp = red + ((ITERS - 1) & 1) * 512;
        float mm = fminf(redp[2 * tid], redp[2 * tid + 1]);
        float y  = tanhf(tanhf(mm));
        const int p  = (ITERS - 1) * 256 + tid;
        const int oy = oy0 + (p >> 8);
        const int ox = p & 255;
        if (ox < OHW && oy < OHW)
            out[((size_t)b * OHW + oy) * OHW + ox] = y;
    }
}

extern "C" void kernel_launch(void* const* d_in, const int* in_sizes, int n_in,
                              void* d_out, int out_size)
{
    const float* x    = (const float*)d_in[0];   // [64,16,256,256]
    const float* w    = (const float*)d_in[1];   // [64,16,3,3]
    const float* bias = (const float*)d_in[2];   // [64]
    float* out = (float*)d_out;                  // [64,1,254,254]

    cudaFuncSetAttribute(conv_mma_kernel,
                         cudaFuncAttributeMaxDynamicSharedMemorySize, SMEM_BYTES);

    dim3 grid(STRIPS, 64);   // 16 strips x 64 images = 1024 CTAs
    conv_mma_kernel<<<grid, 256, SMEM_BYTES>>>(x, w, bias, out);
}

// round 16
// speedup vs baseline: 1.0120x; 1.0120x over previous
#include <cuda_runtime.h>
#include <cuda_bf16.h>
#include <math.h>
#include <stdint.h>

// ---------------- problem constants ----------------
#define OHW         254
#define STRIP_OROWS 16
#define STRIPS      16
#define ITERS       16          // 256 output pixels (one output row) per iteration
#define NCHUNKS     36          // buildable 128-row input chunks per strip
#define RING_ROWS   1280        // 10-chunk ring
#define PITCH       48          // bytes per A/B row (32 data + 16 pad; conflict-free)
#define OFF_B       0           // 9 tiles x 64 rows x 48B = 27648
#define OFF_A       27648
#define SMEM_BYTES  (OFF_A + RING_ROWS * PITCH)     // 89088 (x2 CTAs = 178176)

__device__ __forceinline__ uint32_t smem_u32(const void* p) {
    uint32_t a;
    asm("{ .reg .u64 t; cvta.to.shared.u64 t, %1; cvt.u32.u64 %0, t; }"
        : "=r"(a) : "l"(p));
    return a;
}
__device__ __forceinline__ void ldmatrix_x4(uint32_t& a0, uint32_t& a1,
                                            uint32_t& a2, uint32_t& a3,
                                            uint32_t addr) {
    asm volatile("ldmatrix.sync.aligned.m8n8.x4.shared.b16 {%0,%1,%2,%3}, [%4];"
                 : "=r"(a0), "=r"(a1), "=r"(a2), "=r"(a3) : "r"(addr));
}
__device__ __forceinline__ void mma_bf16(float* c, uint32_t a0, uint32_t a1,
                                         uint32_t a2, uint32_t a3,
                                         uint32_t b0, uint32_t b1) {
    asm volatile(
        "mma.sync.aligned.m16n8k16.row.col.f32.bf16.bf16.f32 "
        "{%0,%1,%2,%3}, {%4,%5,%6,%7}, {%8,%9}, {%0,%1,%2,%3};"
        : "+f"(c[0]), "+f"(c[1]), "+f"(c[2]), "+f"(c[3])
        : "r"(a0), "r"(a1), "r"(a2), "r"(a3), "r"(b0), "r"(b1));
}
__device__ __forceinline__ uint32_t pkbf(float lo, float hi) {
    __nv_bfloat162 t = __float22bfloat162_rn(make_float2(lo, hi));
    return *reinterpret_cast<uint32_t*>(&t);
}

extern __shared__ char smem[];

// Load 16 channel values for one pixel row, converting to 8 packed bf16x2.
__device__ __forceinline__ void load16_u(int c0, int oy0,
                                         const float* __restrict__ xb,
                                         int tid, uint32_t* u) {
    const int p  = c0 * 128 + tid;
    const int iy = oy0 + (p >> 8);
    const int ix = p & 255;
    if (iy < 256) {
        const float* xp = xb + iy * 256 + ix;
        #pragma unroll
        for (int j = 0; j < 8; j++) {
            const float a = __ldg(xp + ((2 * j) << 16));
            const float c = __ldg(xp + ((2 * j + 1) << 16));
            u[j] = pkbf(a, c);
        }
    } else {
        #pragma unroll
        for (int j = 0; j < 8; j++) u[j] = 0u;
    }
}
// Store one staged pixel row at a pre-wrapped ring row.
__device__ __forceinline__ void store16_at(int ring_row, const uint32_t* u) {
    char* base = smem + OFF_A + ring_row * PITCH;
    *reinterpret_cast<uint4*>(base)      = make_uint4(u[0], u[1], u[2], u[3]);
    *reinterpret_cast<uint4*>(base + 16) = make_uint4(u[4], u[5], u[6], u[7]);
}

__global__ __launch_bounds__(256, 2)
void conv_mma_kernel(const float* __restrict__ x, const float* __restrict__ w,
                     const float* __restrict__ bias, float* __restrict__ out)
{
    const int tid  = threadIdx.x;
    const int warp = tid >> 5;        // warp owns rows [warp*32, warp*32+32) of 256
    const int lane = tid & 31;
    const int g    = lane >> 2;       // fragment group (row / n index)
    const int q    = lane & 3;        // thread-in-group

    const int strip = blockIdx.x;
    const int b     = blockIdx.y;
    const int oy0   = strip * STRIP_OROWS;
    const uint32_t sbase = smem_u32(smem);

    // ---- B: 9 tiles (kh*3+kw), rows = cout n, 16 ci bf16 per row ----
    for (int idx = tid; idx < 9 * 64 * 16; idx += 256) {
        const int t  = idx >> 10;
        const int rm = idx & 1023;
        const int n  = rm >> 4;
        const int ci = rm & 15;
        const float val = __ldg(w + n * 144 + ci * 9 + t);
        *reinterpret_cast<__nv_bfloat16*>(smem + OFF_B + t * (64 * PITCH)
                                          + n * PITCH + ci * 2) = __float2bfloat16(val);
    }

    // loop-invariant bias for 8 n-tiles (16 regs): cout = nt*8 + 2q (+1)
    float blo[8], bhi[8];
    #pragma unroll
    for (int nt = 0; nt < 8; nt++) {
        blo[nt] = __ldg(bias + nt * 8 + 2 * q);
        bhi[nt] = __ldg(bias + nt * 8 + 2 * q + 1);
    }

    const float* xb = x + ((size_t)b << 20);

    // lane-constant pieces of ldmatrix addresses
    const uint32_t a_col_off  = (uint32_t)((lane >> 4) << 4);
    const uint32_t b_lane_off = (uint32_t)((((lane >> 3) >> 1) * 8 + (lane & 7)) * PITCH
                                           + (((lane >> 3) & 1) << 4));
    const uint32_t b_base = sbase + OFF_B + b_lane_off;
    const uint32_t a_base = sbase + OFF_A;

    // ---- prologue: chunks 0..7 (rows 0..1023, no wrap) ----
    #pragma unroll 1
    for (int j = 0; j < 4; j++) {
        uint32_t u[8];
        load16_u(2 * j, oy0, xb, tid, u);
        store16_at(2 * j * 128 + tid, u);
    }
    __syncthreads();

    // incremental ring bases (both already in [0, RING_ROWS))
    int sts_row = 1024 + tid;                 // ring row of chunk-8 + tid
    int a_row0  = warp * 32 + (lane & 15);    // warp's M base for i=0

    // ---- main pipeline: ONE barrier per iteration, warp-local epilogue ----
    #pragma unroll 1
    for (int i = 0; i < ITERS; i++) {
        // stage next build's LDGs (chunks 2i+8, 2i+9), convert at load
        const int c0 = 2 * i + 8;
        uint32_t u[8];
        if (c0 < NCHUNKS) load16_u(c0, oy0, xb, tid, u);

        float acc[2][8][4];
        #pragma unroll
        for (int mt = 0; mt < 2; mt++)
            #pragma unroll
            for (int nt = 0; nt < 8; nt++) {
                acc[mt][nt][0] = blo[nt]; acc[mt][nt][1] = bhi[nt];
                acc[mt][nt][2] = blo[nt]; acc[mt][nt][3] = bhi[nt];
            }

        // wrapped kh row bases
        int rks[3];
        #pragma unroll
        for (int kh = 0; kh < 3; kh++) {
            int rk = a_row0 + kh * 256;
            if (rk >= RING_ROWS) rk -= RING_ROWS;
            rks[kh] = rk;
        }

        // 9 shift-steps (reads chunks 2i..2i+6)
        #pragma unroll
        for (int kh = 0; kh < 3; kh++) {
            #pragma unroll
            for (int kw = 0; kw < 3; kw++) {
                const int step = kh * 3 + kw;
                // B fragments for all 8 n-tiles (shared across 2 m-tiles)
                uint32_t bf[16];
                const uint32_t bt = b_base + (uint32_t)(step * 64 * PITCH);
                #pragma unroll
                for (int j = 0; j < 4; j++)
                    ldmatrix_x4(bf[4 * j], bf[4 * j + 1], bf[4 * j + 2],
                                bf[4 * j + 3], bt + (uint32_t)(j * 16 * PITCH));
                #pragma unroll
                for (int mt = 0; mt < 2; mt++) {
                    int row = rks[kh] + kw + mt * 16;
                    if (row >= RING_ROWS) row -= RING_ROWS;
                    uint32_t a0, a1, a2, a3;
                    ldmatrix_x4(a0, a1, a2, a3,
                                a_base + (uint32_t)(row * PITCH) + a_col_off);
                    #pragma unroll
                    for (int nt = 0; nt < 8; nt++)
                        mma_bf16(acc[mt][nt], a0, a1, a2, a3,
                                 bf[2 * nt], bf[2 * nt + 1]);
                }
            }
        }

        // ---- warp-local epilogue: min over ALL 64 couts -> tanh^2 -> store ----
        float m[4];
        #pragma unroll
        for (int mt = 0; mt < 2; mt++) {
            float lo = fminf(acc[mt][0][0], acc[mt][0][1]);
            float hi = fminf(acc[mt][0][2], acc[mt][0][3]);
            #pragma unroll
            for (int nt = 1; nt < 8; nt++) {
                lo = fminf(lo, fminf(acc[mt][nt][0], acc[mt][nt][1]));
                hi = fminf(hi, fminf(acc[mt][nt][2], acc[mt][nt][3]));
            }
            m[2 * mt]     = lo;   // row warp*32 + mt*16 + g
            m[2 * mt + 1] = hi;   // row warp*32 + mt*16 + g + 8
        }
        #pragma unroll
        for (int j = 0; j < 4; j++) {
            m[j] = fminf(m[j], __shfl_xor_sync(0xFFFFFFFFu, m[j], 1));
            m[j] = fminf(m[j], __shfl_xor_sync(0xFFFFFFFFu, m[j], 2));
        }
        if (q == 0) {
            const int oy = oy0 + i;               // iteration == output row
            if (oy < OHW) {
                float* op = out + ((size_t)b * OHW + oy) * OHW;
                const int ox0 = warp * 32 + g;    // +8, +16, +24
                #pragma unroll
                for (int j = 0; j < 4; j++) {
                    const int ox = ox0 + j * 8;
                    if (ox < OHW) op[ox] = tanhf(tanhf(m[j]));
                }
            }
        }

        // commit staged build — chunks 2i+8,2i+9 are disjoint from the read
        // window (2i..2i+6) in the 10-chunk ring
        if (c0 < NCHUNKS) store16_at(sts_row, u);

        // single barrier: orders STS(i) -> ring reads(i+1). No other cross-warp
        // dependencies remain (epilogue is warp-local).
        __syncthreads();

        a_row0 += 256; if (a_row0 >= RING_ROWS) a_row0 -= RING_ROWS;
        sts_row += 256; if (sts_row >= RING_ROWS) sts_row -= RING_ROWS;
    }
}

extern "C" void kernel_launch(void* const* d_in, const int* in_sizes, int n_in,
                              void* d_out, int out_size)
{
    const float* x    = (const float*)d_in[0];   // [64,16,256,256]
    const float* w    = (const float*)d_in[1];   // [64,16,3,3]
    const float* bias = (const float*)d_in[2];   // [64]
    float* out = (float*)d_out;                  // [64,1,254,254]

    cudaFuncSetAttribute(conv_mma_kernel,
                         cudaFuncAttributeMaxDynamicSharedMemorySize, SMEM_BYTES);

    dim3 grid(STRIPS, 64);   // 16 strips x 64 images = 1024 CTAs
    conv_mma_kernel<<<grid, 256, SMEM_BYTES>>>(x, w, bias, out);
}

// round 17
// speedup vs baseline: 1.0259x; 1.0137x over previous
#include <cuda_runtime.h>
#include <cuda_bf16.h>
#include <math.h>
#include <stdint.h>

// ---------------- problem constants ----------------
#define OHW         254
#define STRIP_OROWS 16
#define STRIPS      16
#define ITERS       16          // 256 output pixels per iteration
#define NCHUNKS     36          // buildable 128-row input chunks per strip
#define RING_ROWS   1280        // 10-chunk ring
#define PITCH       48          // bytes per A/B row (32 data + 16 pad; conflict-free)
#define OFF_RED     0           // 2 x 512 floats (ping-pong)
#define OFF_B       4096        // 9 tiles x 64 rows x 48B = 27648
#define OFF_A       (4096 + 27648)                  // 31744
#define SMEM_BYTES  (OFF_A + RING_ROWS * PITCH)     // 93184 (x2 CTAs = 186368)

__device__ __forceinline__ uint32_t smem_u32(const void* p) {
    uint32_t a;
    asm("{ .reg .u64 t; cvta.to.shared.u64 t, %1; cvt.u32.u64 %0, t; }"
        : "=r"(a) : "l"(p));
    return a;
}
__device__ __forceinline__ void ldmatrix_x4(uint32_t& a0, uint32_t& a1,
                                            uint32_t& a2, uint32_t& a3,
                                            uint32_t addr) {
    asm volatile("ldmatrix.sync.aligned.m8n8.x4.shared.b16 {%0,%1,%2,%3}, [%4];"
                 : "=r"(a0), "=r"(a1), "=r"(a2), "=r"(a3) : "r"(addr));
}
__device__ __forceinline__ void mma_bf16(float* c, uint32_t a0, uint32_t a1,
                                         uint32_t a2, uint32_t a3,
                                         uint32_t b0, uint32_t b1) {
    asm volatile(
        "mma.sync.aligned.m16n8k16.row.col.f32.bf16.bf16.f32 "
        "{%0,%1,%2,%3}, {%4,%5,%6,%7}, {%8,%9}, {%0,%1,%2,%3};"
        : "+f"(c[0]), "+f"(c[1]), "+f"(c[2]), "+f"(c[3])
        : "r"(a0), "r"(a1), "r"(a2), "r"(a3), "r"(b0), "r"(b1));
}
__device__ __forceinline__ uint32_t pkbf(float lo, float hi) {
    __nv_bfloat162 t = __float22bfloat162_rn(make_float2(lo, hi));
    return *reinterpret_cast<uint32_t*>(&t);
}
// fast tanh: 1 - 2/(e^{2x}+1); exact limits at +-inf, rel err ~1e-6
__device__ __forceinline__ float tanh_fast(float x) {
    const float e = __expf(2.0f * x);
    return 1.0f - __fdividef(2.0f, e + 1.0f);
}

extern __shared__ char smem[];

// Load 16 channel values for one pixel row, converting to 8 packed bf16x2.
__device__ __forceinline__ void load16_u(int c0, int oy0,
                                         const float* __restrict__ xb,
                                         int tid, uint32_t* u) {
    const int p  = c0 * 128 + tid;
    const int iy = oy0 + (p >> 8);
    const int ix = p & 255;
    if (iy < 256) {
        const float* xp = xb + iy * 256 + ix;
        #pragma unroll
        for (int j = 0; j < 8; j++) {
            const float a = __ldg(xp + ((2 * j) << 16));
            const float c = __ldg(xp + ((2 * j + 1) << 16));
            u[j] = pkbf(a, c);
        }
    } else {
        #pragma unroll
        for (int j = 0; j < 8; j++) u[j] = 0u;
    }
}
// Store one staged pixel row at a pre-wrapped ring row.
__device__ __forceinline__ void store16_at(int ring_row, const uint32_t* u) {
    char* base = smem + OFF_A + ring_row * PITCH;
    *reinterpret_cast<uint4*>(base)      = make_uint4(u[0], u[1], u[2], u[3]);
    *reinterpret_cast<uint4*>(base + 16) = make_uint4(u[4], u[5], u[6], u[7]);
}

// One kh-row of 3 kw shift-steps: 6 B-LDSM + 12 A-LDSM + 48 MMA.
__device__ __forceinline__ void steps3(float (*acc)[4][4], int rk,
                                       uint32_t bh_base, uint32_t a_base,
                                       uint32_t a_col_off) {
    #pragma unroll
    for (int kw = 0; kw < 3; kw++) {
        uint32_t bf[8];
        const uint32_t bt = bh_base + (uint32_t)(kw * 64 * PITCH);
        ldmatrix_x4(bf[0], bf[1], bf[2], bf[3], bt);
        ldmatrix_x4(bf[4], bf[5], bf[6], bf[7], bt + 16 * PITCH);
        #pragma unroll
        for (int mt = 0; mt < 4; mt++) {
            int row = rk + kw + mt * 16;
            if (row >= RING_ROWS) row -= RING_ROWS;
            uint32_t a0, a1, a2, a3;
            ldmatrix_x4(a0, a1, a2, a3,
                        a_base + (uint32_t)(row * PITCH) + a_col_off);
            #pragma unroll
            for (int nt = 0; nt < 4; nt++)
                mma_bf16(acc[mt][nt], a0, a1, a2, a3, bf[2 * nt], bf[2 * nt + 1]);
        }
    }
}

__global__ __launch_bounds__(256, 2)
void conv_mma_kernel(const float* __restrict__ x, const float* __restrict__ w,
                     const float* __restrict__ bias, float* __restrict__ out)
{
    const int tid  = threadIdx.x;
    const int warp = tid >> 5;
    const int lane = tid & 31;
    const int g    = lane >> 2;       // fragment group (row / n index)
    const int q    = lane & 3;        // thread-in-group
    const int nh   = warp & 1;        // n-half: couts [nh*32, nh*32+32)
    const int mq   = warp >> 1;       // m-quarter: rows [mq*64, mq*64+64) of 256

    const int strip = blockIdx.x;
    const int b     = blockIdx.y;
    const int oy0   = strip * STRIP_OROWS;
    const uint32_t sbase = smem_u32(smem);
    float* red = (float*)(smem + OFF_RED);

    // ---- B: 9 tiles (kh*3+kw), rows = cout n, 16 ci bf16 per row ----
    for (int idx = tid; idx < 9 * 64 * 16; idx += 256) {
        const int t  = idx >> 10;
        const int rm = idx & 1023;
        const int n  = rm >> 4;
        const int ci = rm & 15;
        const float val = __ldg(w + n * 144 + ci * 9 + t);
        *reinterpret_cast<__nv_bfloat16*>(smem + OFF_B + t * (64 * PITCH)
                                          + n * PITCH + ci * 2) = __float2bfloat16(val);
    }

    // loop-invariant bias (8 regs)
    float blo[4], bhi[4];
    #pragma unroll
    for (int nt = 0; nt < 4; nt++) {
        blo[nt] = __ldg(bias + nh * 32 + nt * 8 + 2 * q);
        bhi[nt] = __ldg(bias + nh * 32 + nt * 8 + 2 * q + 1);
    }

    const float* xb = x + ((size_t)b << 20);

    // lane-constant pieces of ldmatrix addresses
    const uint32_t a_col_off  = (uint32_t)((lane >> 4) << 4);
    const uint32_t b_lane_off = (uint32_t)((((lane >> 3) >> 1) * 8 + (lane & 7)) * PITCH
                                           + (((lane >> 3) & 1) << 4));
    const uint32_t b_base = sbase + OFF_B + (uint32_t)(nh * 32 * PITCH) + b_lane_off;
    const uint32_t a_base = sbase + OFF_A;

    // ---- prologue: chunks 0..7 (rows 0..1023, no wrap) ----
    #pragma unroll 1
    for (int j = 0; j < 4; j++) {
        uint32_t u[8];
        load16_u(2 * j, oy0, xb, tid, u);
        store16_at(2 * j * 128 + tid, u);
    }
    __syncthreads();

    // incremental ring bases (both already in [0, RING_ROWS))
    int sts_row = 1024 + tid;                 // ring row of chunk-8 + tid
    int a_row0  = mq * 64 + (lane & 15);      // warp's M base for i=0

    // acc for the CURRENT iteration; kh=0 of iteration 0 hoisted here
    float acc[4][4][4];
    #pragma unroll
    for (int mt = 0; mt < 4; mt++)
        #pragma unroll
        for (int nt = 0; nt < 4; nt++) {
            acc[mt][nt][0] = blo[nt]; acc[mt][nt][1] = bhi[nt];
            acc[mt][nt][2] = blo[nt]; acc[mt][nt][3] = bhi[nt];
        }
    steps3(acc, a_row0, b_base, a_base, a_col_off);   // kh=0, iter 0

    // ---- main pipeline: ONE barrier/iter, kh=0(i+1) hoisted across it ----
    #pragma unroll 1
    for (int i = 0; i < ITERS; i++) {
        // deferred epilogue part 2 of iteration i-1
        if (i > 0) {
            const float* redp = red + ((i - 1) & 1) * 512;
            float mm = fminf(redp[2 * tid], redp[2 * tid + 1]);
            float y  = tanh_fast(tanh_fast(mm));
            const int p  = (i - 1) * 256 + tid;
            const int oy = oy0 + (p >> 8);
            const int ox = p & 255;
            if (ox < OHW && oy < OHW)
                out[((size_t)b * OHW + oy) * OHW + ox] = y;
        }

        // stage next build's LDGs (chunks 2i+8, 2i+9), convert at load
        const int c0 = 2 * i + 8;
        uint32_t u[8];
        if (c0 < NCHUNKS) load16_u(c0, oy0, xb, tid, u);

        // kh=1 and kh=2 of iteration i (kh=0 already accumulated pre-barrier)
        int rk1 = a_row0 + 256; if (rk1 >= RING_ROWS) rk1 -= RING_ROWS;
        int rk2 = rk1 + 256;    if (rk2 >= RING_ROWS) rk2 -= RING_ROWS;
        steps3(acc, rk1, b_base + (uint32_t)(3 * 64 * PITCH), a_base, a_col_off);
        steps3(acc, rk2, b_base + (uint32_t)(6 * 64 * PITCH), a_base, a_col_off);

        // ---- epilogue part 1: min over this warp's 32 couts -> red[i&1] ----
        float m[8];
        #pragma unroll
        for (int mt = 0; mt < 4; mt++) {
            float lo = fminf(acc[mt][0][0], acc[mt][0][1]);
            float hi = fminf(acc[mt][0][2], acc[mt][0][3]);
            #pragma unroll
            for (int nt = 1; nt < 4; nt++) {
                lo = fminf(lo, fminf(acc[mt][nt][0], acc[mt][nt][1]));
                hi = fminf(hi, fminf(acc[mt][nt][2], acc[mt][nt][3]));
            }
            m[2 * mt]     = lo;   // row mq*64 + mt*16 + g
            m[2 * mt + 1] = hi;   // row mq*64 + mt*16 + g + 8
        }
        #pragma unroll
        for (int j = 0; j < 8; j++) {
            m[j] = fminf(m[j], __shfl_xor_sync(0xFFFFFFFFu, m[j], 1));
            m[j] = fminf(m[j], __shfl_xor_sync(0xFFFFFFFFu, m[j], 2));
        }
        float* redp = red + (i & 1) * 512;
        if (q == 0) {
            const int rb = mq * 64 + g;
            #pragma unroll
            for (int j = 0; j < 8; j++)
                redp[(rb + j * 8) * 2 + nh] = m[j];
        }

        // commit staged build — chunks 2i+8,2i+9 disjoint from read window
        if (c0 < NCHUNKS) store16_at(sts_row, u);

        // advance the M base; then HOIST kh=0 of iteration i+1 BEFORE the
        // barrier. It reads chunks 2i+2..2i+4: built >=2 iterations ago
        // (ordered by barrier(i-2)) and disjoint from this STS (2i+8,2i+9).
        a_row0 += 256; if (a_row0 >= RING_ROWS) a_row0 -= RING_ROWS;
        if (i + 1 < ITERS) {
            #pragma unroll
            for (int mt = 0; mt < 4; mt++)
                #pragma unroll
                for (int nt = 0; nt < 4; nt++) {
                    acc[mt][nt][0] = blo[nt]; acc[mt][nt][1] = bhi[nt];
                    acc[mt][nt][2] = blo[nt]; acc[mt][nt][3] = bhi[nt];
                }
            steps3(acc, a_row0, b_base, a_base, a_col_off);   // kh=0, iter i+1
        }

        // single barrier: STS(i)->reads(i+1 kh=1,2); red write->part2 read;
        // part2(i-1) read -> red rewrite (i+1)
        __syncthreads();

        sts_row += 256; if (sts_row >= RING_ROWS) sts_row -= RING_ROWS;
    }

    // final deferred epilogue (iteration ITERS-1)
    {
        const float* redp = red + ((ITERS - 1) & 1) * 512;
        float mm = fminf(redp[2 * tid], redp[2 * tid + 1]);
        float y  = tanh_fast(tanh_fast(mm));
        const int p  = (ITERS - 1) * 256 + tid;
        const int oy = oy0 + (p >> 8);
        const int ox = p & 255;
        if (ox < OHW && oy < OHW)
            out[((size_t)b * OHW + oy) * OHW + ox] = y;
    }
}

extern "C" void kernel_launch(void* const* d_in, const int* in_sizes, int n_in,
                              void* d_out, int out_size)
{
    const float* x    = (const float*)d_in[0];   // [64,16,256,256]
    const float* w    = (const float*)d_in[1];   // [64,16,3,3]
    const float* bias = (const float*)d_in[2];   // [64]
    float* out = (float*)d_out;                  // [64,1,254,254]

    cudaFuncSetAttribute(conv_mma_kernel,
                         cudaFuncAttributeMaxDynamicSharedMemorySize, SMEM_BYTES);

    dim3 grid(STRIPS, 64);   // 16 strips x 64 images = 1024 CTAs
    conv_mma_kernel<<<grid, 256, SMEM_BYTES>>>(x, w, bias, out);
}